// round 1
// baseline (speedup 1.0000x reference)
#include <cuda_runtime.h>

#define B_ 16
#define T_ 8192
#define D_ 128
#define C_ 64
#define N_ 128

// Scratch (no allocation allowed): wo / per-chunk pre-state, and k_sum / pre-z.
__device__ float g_wo[(size_t)B_ * N_ * D_ * D_];   // 128 MB
__device__ float g_ks[(size_t)B_ * N_ * D_];        // 1 MB

__device__ __forceinline__ float lam_from(const float* __restrict__ ld) {
    return 1.0f / (1.0f + __expf(-ld[0]));
}

// ---------------------------------------------------------------------------
// Kernel A: per-chunk weighted outer product wo = (cd*K)^T V  and ksum.
// grid (N_, B_), 256 threads. smem: K tile (scaled), V tile, cd table.
// ---------------------------------------------------------------------------
__global__ __launch_bounds__(256) void wo_kernel(
    const float* __restrict__ k, const float* __restrict__ v,
    const float* __restrict__ ld)
{
    extern __shared__ float sm[];
    float* sk  = sm;                 // [64][128]  (pre-scaled by chunk_decay)
    float* sv  = sm + C_ * D_;       // [64][128]
    float* scd = sm + 2 * C_ * D_;   // [64]
    const int tid = threadIdx.x;
    const int n = blockIdx.x, b = blockIdx.y;

    const float lam = lam_from(ld);
    if (tid < C_) scd[tid] = powf(lam, (float)(C_ - 1 - tid));
    __syncthreads();

    const size_t base = ((size_t)b * T_ + (size_t)n * C_) * D_;
    for (int idx = tid; idx < C_ * D_; idx += 256) {
        int c = idx >> 7;
        sk[idx] = k[base + idx] * scd[c];
        sv[idx] = v[base + idx];
    }
    __syncthreads();

    const int ty = tid >> 4, tx = tid & 15;
    const int i0 = ty * 8, j0 = tx * 8;
    float acc[8][8];
#pragma unroll
    for (int u = 0; u < 8; u++)
#pragma unroll
        for (int w = 0; w < 8; w++) acc[u][w] = 0.f;

#pragma unroll 2
    for (int c = 0; c < C_; c++) {
        float4 a0 = *(const float4*)&sk[c * D_ + i0];
        float4 a1 = *(const float4*)&sk[c * D_ + i0 + 4];
        float4 b0 = *(const float4*)&sv[c * D_ + j0];
        float4 b1 = *(const float4*)&sv[c * D_ + j0 + 4];
        float av[8] = {a0.x, a0.y, a0.z, a0.w, a1.x, a1.y, a1.z, a1.w};
        float bv[8] = {b0.x, b0.y, b0.z, b0.w, b1.x, b1.y, b1.z, b1.w};
#pragma unroll
        for (int u = 0; u < 8; u++)
#pragma unroll
            for (int w = 0; w < 8; w++)
                acc[u][w] = fmaf(av[u], bv[w], acc[u][w]);
    }

    float* wbase = g_wo + (((size_t)b * N_ + n) << 14);
#pragma unroll
    for (int u = 0; u < 8; u++) {
        float4 s0 = make_float4(acc[u][0], acc[u][1], acc[u][2], acc[u][3]);
        float4 s1 = make_float4(acc[u][4], acc[u][5], acc[u][6], acc[u][7]);
        *(float4*)&wbase[(i0 + u) * D_ + j0]     = s0;
        *(float4*)&wbase[(i0 + u) * D_ + j0 + 4] = s1;
    }

    if (tid < D_) {
        float s = 0.f;
#pragma unroll 8
        for (int c = 0; c < C_; c++) s += sk[c * D_ + tid];
        g_ks[((size_t)b * N_ + n) * D_ + tid] = s;
    }
}

// ---------------------------------------------------------------------------
// Kernel B: in-place prefix scan over chunks. Each element of wo is replaced
// by the state BEFORE that chunk; final state goes to d_out state region.
// 262144 threads, 128 sequential steps each.
// ---------------------------------------------------------------------------
__global__ __launch_bounds__(256) void scan_state_kernel(
    const float* __restrict__ ld, float* __restrict__ out_state)
{
    const int gid = blockIdx.x * 256 + threadIdx.x;       // [0, B*D*D)
    const int b = gid >> 14;
    const int idx = gid & 16383;
    const float lam = lam_from(ld);
    const float r = powf(lam, (float)C_);
    float s = 0.f;
    float* p = g_wo + (((size_t)b * N_) << 14) + idx;
#pragma unroll 4
    for (int n = 0; n < N_; n++) {
        float w = p[(size_t)n << 14];
        p[(size_t)n << 14] = s;
        s = fmaf(r, s, w);
    }
    out_state[gid] = s;
}

__global__ __launch_bounds__(256) void scan_z_kernel(
    const float* __restrict__ ld, float* __restrict__ out_z)
{
    const int gid = blockIdx.x * 256 + threadIdx.x;       // [0, B*D)
    const int b = gid >> 7;
    const int d = gid & 127;
    const float lam = lam_from(ld);
    const float r = powf(lam, (float)C_);
    float s = 0.f;
    float* p = g_ks + (size_t)b * N_ * D_ + d;
#pragma unroll 4
    for (int n = 0; n < N_; n++) {
        float w = p[n * D_];
        p[n * D_] = s;
        s = fmaf(r, s, w);
    }
    out_z[gid] = s;
}

// ---------------------------------------------------------------------------
// Kernel C: per-chunk output.
//   attn  = (Q K^T) .* decay_mask        (64x64, k=128)
//   intra = attn V                        (64x128, k=64)
//   cross = Q state                       (64x128, k=128)
//   out   = (intra + decay_q[i]*cross) / max(max(rowsum,1)+decay_q[i]*(z.q),1)
// grid (N_, B_), 256 threads, ~189 KB smem.
// ---------------------------------------------------------------------------
__global__ __launch_bounds__(256) void out_kernel(
    const float* __restrict__ q, const float* __restrict__ k,
    const float* __restrict__ v, const float* __restrict__ ld,
    float* __restrict__ out)
{
    extern __shared__ float sm[];
    float* sqT  = sm;                  // [128][68]  Q transposed (d-major)
    float* skT  = sqT + 128 * 68;      // [128][68]  K transposed
    float* svv  = skT + 128 * 68;      // [64][132]  V row-major padded
    float* sst  = svv + 64 * 132;      // [128][132] state row-major padded
    float* sat  = sst + 128 * 132;     // [64][68]   attn i-major padded
    float* spw  = sat + 64 * 68;       // [68]       lam^t
    float* szv  = spw + 68;            // [128]      pre-chunk z
    float* sinv = szv + 128;           // [64]       1/total_z

    const int tid = threadIdx.x;
    const int n = blockIdx.x, b = blockIdx.y;
    const float lam = lam_from(ld);
    if (tid <= C_) spw[tid] = powf(lam, (float)tid);

    const size_t base = ((size_t)b * T_ + (size_t)n * C_) * D_;
    for (int idx = tid; idx < C_ * D_; idx += 256) {
        int c = idx >> 7, d = idx & 127;
        sqT[d * 68 + c] = q[base + idx];
        skT[d * 68 + c] = k[base + idx];
        svv[c * 132 + d] = v[base + idx];
    }
    {
        const float* st = g_wo + (((size_t)b * N_ + n) << 14);
        for (int idx = tid; idx < D_ * D_; idx += 256)
            sst[(idx >> 7) * 132 + (idx & 127)] = st[idx];
    }
    if (tid < D_) szv[tid] = g_ks[((size_t)b * N_ + n) * D_ + tid];
    __syncthreads();

    const int ty = tid >> 4, tx = tid & 15;
    const int i0 = ty * 4, j0 = tx * 4;

    // ---- GEMM1: S = Q K^T (64x64, k=128) ----
    float a1[4][4];
#pragma unroll
    for (int u = 0; u < 4; u++)
#pragma unroll
        for (int w = 0; w < 4; w++) a1[u][w] = 0.f;
#pragma unroll 4
    for (int d = 0; d < D_; d++) {
        float4 a  = *(const float4*)&sqT[d * 68 + i0];
        float4 bb = *(const float4*)&skT[d * 68 + j0];
        float av[4] = {a.x, a.y, a.z, a.w};
        float bv[4] = {bb.x, bb.y, bb.z, bb.w};
#pragma unroll
        for (int u = 0; u < 4; u++)
#pragma unroll
            for (int w = 0; w < 4; w++)
                a1[u][w] = fmaf(av[u], bv[w], a1[u][w]);
    }
    // mask + decay, write i-major
#pragma unroll
    for (int u = 0; u < 4; u++) {
        int i = i0 + u;
#pragma unroll
        for (int w = 0; w < 4; w++) {
            int j = j0 + w;
            float val = (j <= i) ? a1[u][w] * spw[i - j] : 0.f;
            sat[i * 68 + j] = val;
        }
    }
    __syncthreads();

    // ---- z normalization terms (threads 0..63, one row each) ----
    if (tid < C_) {
        const int i = tid;
        float rs = 0.f;
#pragma unroll 8
        for (int j = 0; j < C_; j++) rs += sat[i * 68 + j];
        float cz = 0.f;
#pragma unroll 8
        for (int d = 0; d < D_; d++) cz = fmaf(szv[d], sqT[d * 68 + i], cz);
        float dq = spw[i + 1];
        float iz = fmaxf(rs, 1.f);
        float tz = fmaxf(iz + dq * cz, 1.f);
        sinv[i] = 1.f / tz;
    }

    const int c0 = tx * 8;

    // ---- GEMM3: cross = Q state (64x128, k=128) ----
    float o2[4][8];
#pragma unroll
    for (int u = 0; u < 4; u++)
#pragma unroll
        for (int w = 0; w < 8; w++) o2[u][w] = 0.f;
#pragma unroll 2
    for (int d = 0; d < D_; d++) {
        float4 a  = *(const float4*)&sqT[d * 68 + i0];
        float av[4] = {a.x, a.y, a.z, a.w};
        float4 b0 = *(const float4*)&sst[d * 132 + c0];
        float4 b1 = *(const float4*)&sst[d * 132 + c0 + 4];
        float bv[8] = {b0.x, b0.y, b0.z, b0.w, b1.x, b1.y, b1.z, b1.w};
#pragma unroll
        for (int u = 0; u < 4; u++)
#pragma unroll
            for (int w = 0; w < 8; w++)
                o2[u][w] = fmaf(av[u], bv[w], o2[u][w]);
    }

    // ---- GEMM2: intra = attn V (64x128, k=64) ----
    float o1[4][8];
#pragma unroll
    for (int u = 0; u < 4; u++)
#pragma unroll
        for (int w = 0; w < 8; w++) o1[u][w] = 0.f;
#pragma unroll 2
    for (int j = 0; j < C_; j++) {
        float av[4];
#pragma unroll
        for (int u = 0; u < 4; u++) av[u] = sat[(i0 + u) * 68 + j];
        float4 b0 = *(const float4*)&svv[j * 132 + c0];
        float4 b1 = *(const float4*)&svv[j * 132 + c0 + 4];
        float bv[8] = {b0.x, b0.y, b0.z, b0.w, b1.x, b1.y, b1.z, b1.w};
#pragma unroll
        for (int u = 0; u < 4; u++)
#pragma unroll
            for (int w = 0; w < 8; w++)
                o1[u][w] = fmaf(av[u], bv[w], o1[u][w]);
    }
    __syncthreads();   // sinv visible to all

    // ---- combine + store ----
    float* ob = out + base;
#pragma unroll
    for (int u = 0; u < 4; u++) {
        int i = i0 + u;
        float dq  = spw[i + 1];
        float inv = sinv[i];
        float4 r0, r1;
        r0.x = fmaf(dq, o2[u][0], o1[u][0]) * inv;
        r0.y = fmaf(dq, o2[u][1], o1[u][1]) * inv;
        r0.z = fmaf(dq, o2[u][2], o1[u][2]) * inv;
        r0.w = fmaf(dq, o2[u][3], o1[u][3]) * inv;
        r1.x = fmaf(dq, o2[u][4], o1[u][4]) * inv;
        r1.y = fmaf(dq, o2[u][5], o1[u][5]) * inv;
        r1.z = fmaf(dq, o2[u][6], o1[u][6]) * inv;
        r1.w = fmaf(dq, o2[u][7], o1[u][7]) * inv;
        *(float4*)&ob[i * D_ + c0]     = r0;
        *(float4*)&ob[i * D_ + c0 + 4] = r1;
    }
}

// ---------------------------------------------------------------------------
extern "C" void kernel_launch(void* const* d_in, const int* in_sizes, int n_in,
                              void* d_out, int out_size)
{
    const float* q  = (const float*)d_in[0];
    const float* k  = (const float*)d_in[1];
    const float* v  = (const float*)d_in[2];
    const float* ld = (const float*)d_in[3];
    float* out = (float*)d_out;

    const int smemA = (2 * C_ * D_ + C_) * (int)sizeof(float);     // ~66 KB
    const int smemC = (128 * 68 * 2 + 64 * 132 + 128 * 132 + 64 * 68 + 68 + 128 + 64)
                      * (int)sizeof(float);                        // ~189 KB
    cudaFuncSetAttribute(wo_kernel,  cudaFuncAttributeMaxDynamicSharedMemorySize, smemA);
    cudaFuncSetAttribute(out_kernel, cudaFuncAttributeMaxDynamicSharedMemorySize, smemC);

    dim3 grid(N_, B_);
    float* out_state = out + (size_t)B_ * T_ * D_;                 // [B,D,D]
    float* out_z     = out_state + (size_t)B_ * D_ * D_;           // [B,D]

    wo_kernel<<<grid, 256, smemA>>>(k, v, ld);
    scan_state_kernel<<<(B_ * D_ * D_) / 256, 256>>>(ld, out_state);
    scan_z_kernel<<<(B_ * D_) / 256, 256>>>(ld, out_z);
    out_kernel<<<grid, 256, smemC>>>(q, k, v, ld, out);
}